// round 3
// baseline (speedup 1.0000x reference)
#include <cuda_runtime.h>

// ---------------------------------------------------------------------------
// Problem constants
// ---------------------------------------------------------------------------
constexpr int Bv = 16, Nv = 2048, Tv = 48, Ev = 32;
constexpr int C0 = 64, C1 = 64, H1 = 256, H2 = 128, NPRED = 12;
constexpr int SEQS = Bv * Nv;          // 32768
constexpr int PAIRS = SEQS / 2;        // 16384
constexpr int HSTRIDE = 65;            // padded row stride for h (bank-conflict free)
constexpr int HSIZE = Tv * HSTRIDE;    // 3120

// ---------------------------------------------------------------------------
// Device-global scratch (no allocations allowed)
// ---------------------------------------------------------------------------
__device__ float g_Wf[96 * 64];        // folded W_in @ W_conv[k], [k*32+e][c]
__device__ float g_WqkT[64 * 64];      // (Wk Wq^T) transposed: [c'][c]
__device__ float g_bqk[64];            // Wk @ bq
__device__ float g_vqb[64];            // Wq @ bk
__device__ float g_bias3[3 * 64];      // conv bias for t==0 / interior / t==47
__device__ float g_sqb;                // bq . bk
__device__ float g_ctx[(size_t)SEQS * 64];  // attention output, 8MB

// ---------------------------------------------------------------------------
// Prep kernel: fold weights (tiny, ~650K MACs)
// ---------------------------------------------------------------------------
__global__ void prep_kernel(const float* __restrict__ W_in, const float* __restrict__ b_in,
                            const float* __restrict__ W_conv, const float* __restrict__ b_conv,
                            const float* __restrict__ Wq, const float* __restrict__ bq,
                            const float* __restrict__ Wk, const float* __restrict__ bk) {
    int idx = blockIdx.x * blockDim.x + threadIdx.x;
    if (idx < 6144) {
        // Wf[k*32+e][c] = sum_m W_in[e][m] * W_conv[k][m][c]
        int row = idx >> 6, c = idx & 63;
        int k = row >> 5, e = row & 31;
        float s = 0.f;
        #pragma unroll 8
        for (int m = 0; m < 64; m++)
            s = fmaf(W_in[e * 64 + m], W_conv[(k * 64 + m) * 64 + c], s);
        g_Wf[row * 64 + c] = s;
    } else if (idx < 10240) {
        // WqkT[c'][c] = sum_d Wk[c][d] * Wq[c'][d]
        int i = idx - 6144;
        int cp = i >> 6, c = i & 63;
        float s = 0.f;
        #pragma unroll 8
        for (int d = 0; d < 64; d++)
            s = fmaf(Wk[c * 64 + d], Wq[cp * 64 + d], s);
        g_WqkT[cp * 64 + c] = s;
    } else if (idx < 10304) {
        int c = idx - 10240;
        float s = 0.f;
        #pragma unroll 8
        for (int d = 0; d < 64; d++) s = fmaf(Wk[c * 64 + d], bq[d], s);
        g_bqk[c] = s;
    } else if (idx < 10368) {
        int cp = idx - 10304;
        float s = 0.f;
        #pragma unroll 8
        for (int d = 0; d < 64; d++) s = fmaf(Wq[cp * 64 + d], bk[d], s);
        g_vqb[cp] = s;
    } else if (idx < 10560) {
        int i = idx - 10368;
        int which = i >> 6, c = i & 63;  // 0: t==0, 1: interior, 2: t==47
        float gb[3];
        #pragma unroll
        for (int k = 0; k < 3; k++) {
            float s = 0.f;
            #pragma unroll 8
            for (int m = 0; m < 64; m++)
                s = fmaf(b_in[m], W_conv[(k * 64 + m) * 64 + c], s);
            gb[k] = s;
        }
        float r = b_conv[c];
        if (which == 0)      r += gb[1] + gb[2];          // tap k=0 reads zero pad
        else if (which == 1) r += gb[0] + gb[1] + gb[2];
        else                 r += gb[0] + gb[1];          // tap k=2 reads zero pad
        g_bias3[which * 64 + c] = r;
    } else if (idx == 10560) {
        float s = 0.f;
        for (int d = 0; d < 64; d++) s = fmaf(bq[d], bk[d], s);
        g_sqb = s;
    }
}

// ---------------------------------------------------------------------------
// Main fused kernel smem layout (floats)
// ---------------------------------------------------------------------------
constexpr int SM_WF    = 0;                 // 6144
constexpr int SM_WQKT  = 6144;              // 4096
constexpr int SM_WV    = 10240;             // 4096
constexpr int SM_BV    = 14336;             // 64
constexpr int SM_BQK   = 14400;             // 64
constexpr int SM_VQB   = 14464;             // 64
constexpr int SM_BIAS3 = 14528;             // 192
constexpr int SM_X     = 14720;             // 2*1536 = 3072
constexpr int SM_H     = 17792;             // 2*3120 = 6240
constexpr int SM_KQ    = 24032;             // 128
constexpr int SM_SC    = 24160;             // 96
constexpr int SM_P     = 24256;             // 96
constexpr int SM_HB    = 24352;             // 128
constexpr int SM_MISC  = 24480;             // 8: bias[2], max[2], rinv[2], sqb
constexpr int MAIN_SMEM_FLOATS = 24488;
constexpr int MAIN_SMEM_BYTES  = MAIN_SMEM_FLOATS * 4;   // 97952

// Folded conv for 24 timesteps starting at compile-time T0.
// Thread owns column c; x values rolled through registers: 1 LDS + 3 FFMA per t.
template <int T0>
__device__ __forceinline__ void conv_part(const float* __restrict__ xs,
                                          const float* __restrict__ s,
                                          float* hacc, int c) {
    #pragma unroll
    for (int tt = 0; tt < 24; tt++) {
        int t = T0 + tt;
        const float* b = (t == 0) ? (s + SM_BIAS3)
                        : (t == 47 ? (s + SM_BIAS3 + 128) : (s + SM_BIAS3 + 64));
        hacc[tt] = b[c];
    }
    const float* wf = s + SM_WF + c;
    #pragma unroll 2
    for (int e = 0; e < 32; e++) {
        float w0 = wf[e * 64];
        float w1 = wf[(32 + e) * 64];
        float w2 = wf[(64 + e) * 64];
        const float* xb = xs + e;
        float xm = (T0 == 0) ? 0.0f : xb[(T0 - 1) * 32];
        float xc = xb[T0 * 32];
        #pragma unroll
        for (int tt = 0; tt < 24; tt++) {
            float xp = (T0 + tt == 47) ? 0.0f : xb[(T0 + tt + 1) * 32];
            hacc[tt] = fmaf(w0, xm, hacc[tt]);
            hacc[tt] = fmaf(w1, xc, hacc[tt]);
            hacc[tt] = fmaf(w2, xp, hacc[tt]);
            xm = xc; xc = xp;
        }
    }
}

// ---------------------------------------------------------------------------
// Main fused kernel: folded conv + collapsed attention, 2 sequences per iter
// ---------------------------------------------------------------------------
__global__ void __launch_bounds__(256, 2)
main_kernel(const float* __restrict__ x, const float* __restrict__ Wv,
            const float* __restrict__ bv) {
    extern __shared__ float s[];
    const int tid = threadIdx.x;

    // Stage weights into smem (once per block; blocks are persistent)
    for (int i = tid; i < 6144; i += 256) s[SM_WF + i] = g_Wf[i];
    for (int i = tid; i < 4096; i += 256) s[SM_WQKT + i] = g_WqkT[i];
    for (int i = tid; i < 4096; i += 256) s[SM_WV + i] = Wv[i];
    if (tid < 64) {
        s[SM_BV + tid]         = bv[tid];
        s[SM_BQK + tid]        = g_bqk[tid];
        s[SM_VQB + tid]        = g_vqb[tid];
        s[SM_BIAS3 + tid]       = g_bias3[tid];
        s[SM_BIAS3 + 64 + tid]  = g_bias3[64 + tid];
        s[SM_BIAS3 + 128 + tid] = g_bias3[128 + tid];
    }
    if (tid == 0) s[SM_MISC + 6] = g_sqb;

    const int c    = tid & 63;
    const int sub  = tid >> 6;   // 0..3
    const int useq = sub >> 1;   // conv: which of the 2 sequences
    const int tg   = sub & 1;    // conv: which 24-timestep half
    const int r    = tid & 127;  // attention role within half
    const int u    = tid >> 7;   // attention: which sequence

    int pi = blockIdx.x;
    // prefetch first pair's x (2 seqs contiguous = 3072 floats = 768 float4)
    float4 xr0, xr1, xr2;
    {
        const float4* src = (const float4*)(x + (size_t)pi * 3072);
        xr0 = src[tid]; xr1 = src[tid + 256]; xr2 = src[tid + 512];
    }

    for (; pi < PAIRS; pi += gridDim.x) {
        // commit prefetched x to smem, then prefetch next pair (hides DRAM latency)
        {
            float4* xd = (float4*)(s + SM_X);
            xd[tid] = xr0; xd[tid + 256] = xr1; xd[tid + 512] = xr2;
            int np = pi + gridDim.x;
            const float4* src = (const float4*)(x + (size_t)(np < PAIRS ? np : 0) * 3072);
            xr0 = src[tid]; xr1 = src[tid + 256]; xr2 = src[tid + 512];
        }
        __syncthreads();

        // ---- folded conv (fp32 fma-bound core) ----
        float hacc[24];
        const float* xs = s + SM_X + useq * 1536;
        float* hs = s + SM_H + useq * HSIZE;
        if (tg == 0) conv_part<0>(xs, s, hacc, c);
        else         conv_part<24>(xs, s, hacc, c);
        {
            const int t0 = tg * 24;
            #pragma unroll
            for (int tt = 0; tt < 24; tt++)
                hs[(t0 + tt) * HSTRIDE + c] = fmaxf(hacc[tt], 0.0f);
        }
        __syncthreads();

        // ---- collapsed attention (per 128-thread half) ----
        const float* hu = s + SM_H + u * HSIZE;
        float score = 0.f, p = 0.f;

        // stage 1: kq[c] = bqk + h47 . WqkT[:,c] ; bias = sqb + h47 . vqb
        if (r < 64) {
            float acc = s[SM_BQK + r];
            const float* h47 = hu + 47 * HSTRIDE;
            #pragma unroll 8
            for (int cp = 0; cp < 64; cp++)
                acc = fmaf(h47[cp], s[SM_WQKT + cp * 64 + r], acc);
            s[SM_KQ + u * 64 + r] = acc;
        } else if (r == 64) {
            float acc = s[SM_MISC + 6];
            const float* h47 = hu + 47 * HSTRIDE;
            #pragma unroll 8
            for (int cp = 0; cp < 64; cp++)
                acc = fmaf(h47[cp], s[SM_VQB + cp], acc);
            s[SM_MISC + u] = acc;
        }
        __syncthreads();

        // stage 2: scores[s] = (h[s].kq + bias) / 8
        if (r < 48) {
            float acc = 0.f;
            const float* hrow = hu + r * HSTRIDE;
            #pragma unroll 8
            for (int cc = 0; cc < 64; cc++)
                acc = fmaf(hrow[cc], s[SM_KQ + u * 64 + cc], acc);
            score = (acc + s[SM_MISC + u]) * 0.125f;
            s[SM_SC + u * 48 + r] = score;
        }
        __syncthreads();

        // stage 3: max-reduce (one warp per half)
        if (r < 32) {
            float v = s[SM_SC + u * 48 + r];
            if (r < 16) v = fmaxf(v, s[SM_SC + u * 48 + 32 + r]);
            #pragma unroll
            for (int off = 16; off; off >>= 1)
                v = fmaxf(v, __shfl_xor_sync(0xffffffffu, v, off));
            if (r == 0) s[SM_MISC + 2 + u] = v;
        }
        __syncthreads();

        // stage 4: exp
        if (r < 48) {
            p = __expf(score - s[SM_MISC + 2 + u]);
            s[SM_P + u * 48 + r] = p;
        }
        __syncthreads();

        // stage 5: sum-reduce -> 1/sum
        if (r < 32) {
            float v = s[SM_P + u * 48 + r];
            if (r < 16) v += s[SM_P + u * 48 + 32 + r];
            #pragma unroll
            for (int off = 16; off; off >>= 1)
                v += __shfl_xor_sync(0xffffffffu, v, off);
            if (r == 0) s[SM_MISC + 4 + u] = 1.0f / v;
        }
        __syncthreads();

        // stage 6: hbar[c] = (sum_s p[s] h[s][c]) / sum
        if (r < 64) {
            float acc = 0.f;
            #pragma unroll 8
            for (int ss = 0; ss < 48; ss++)
                acc = fmaf(s[SM_P + u * 48 + ss], hu[ss * HSTRIDE + r], acc);
            s[SM_HB + u * 64 + r] = acc * s[SM_MISC + 4 + u];
        }
        __syncthreads();

        // stage 7: ctx = hbar @ Wv + bv  -> global scratch
        if (r < 64) {
            float acc = s[SM_BV + r];
            #pragma unroll 8
            for (int cc = 0; cc < 64; cc++)
                acc = fmaf(s[SM_HB + u * 64 + cc], s[SM_WV + cc * 64 + r], acc);
            g_ctx[(size_t)(2 * pi + u) * 64 + r] = acc;
        }
        // no trailing sync needed: next-iter writes are fenced by the loop-top sync
    }
}

// ---------------------------------------------------------------------------
// MLP kernel: 32 sequences per block; W1/W2 streamed from L2 (resident)
// ---------------------------------------------------------------------------
constexpr int M_SM_CTX = 0;        // 32*64  = 2048
constexpr int M_SM_Z1  = 2048;     // 32*256 = 8192
constexpr int M_SM_Z2  = 10240;    // 32*129 = 4128 (padded: conflict-free L3 reads)
constexpr int M_SM_W3  = 14368;    // 128*12 = 1536
constexpr int M_SM_B3  = 15904;    // 12
constexpr int MLP_SMEM_FLOATS = 15920;
constexpr int MLP_SMEM_BYTES  = MLP_SMEM_FLOATS * 4;    // 63680

__global__ void __launch_bounds__(256)
mlp_kernel(const float* __restrict__ W1, const float* __restrict__ b1,
           const float* __restrict__ W2, const float* __restrict__ b2,
           const float* __restrict__ W3, const float* __restrict__ b3,
           float* __restrict__ out) {
    extern __shared__ float s[];
    const int tid = threadIdx.x;
    const int m0 = blockIdx.x * 32;

    {
        const float4* src = (const float4*)(g_ctx + (size_t)m0 * 64);
        float4* dst = (float4*)(s + M_SM_CTX);
        dst[tid] = src[tid];
        dst[tid + 256] = src[tid + 256];
    }
    for (int i = tid; i < 1536; i += 256) s[M_SM_W3 + i] = W3[i];
    if (tid < 12) s[M_SM_B3 + tid] = b3[tid];
    __syncthreads();

    // layer 1: z1[m][j] = relu(ctx[m] . W1[:,j] + b1[j]), thread owns column j=tid
    {
        float acc[32];
        const float bj = b1[tid];
        #pragma unroll
        for (int m = 0; m < 32; m++) acc[m] = bj;
        const float4* ctx4 = (const float4*)(s + M_SM_CTX);
        #pragma unroll 4
        for (int k4 = 0; k4 < 16; k4++) {
            float w0 = W1[(4 * k4 + 0) * 256 + tid];
            float w1 = W1[(4 * k4 + 1) * 256 + tid];
            float w2 = W1[(4 * k4 + 2) * 256 + tid];
            float w3 = W1[(4 * k4 + 3) * 256 + tid];
            #pragma unroll
            for (int m = 0; m < 32; m++) {
                float4 cv = ctx4[m * 16 + k4];
                acc[m] = fmaf(w0, cv.x, acc[m]);
                acc[m] = fmaf(w1, cv.y, acc[m]);
                acc[m] = fmaf(w2, cv.z, acc[m]);
                acc[m] = fmaf(w3, cv.w, acc[m]);
            }
        }
        #pragma unroll
        for (int m = 0; m < 32; m++)
            s[M_SM_Z1 + m * 256 + tid] = fmaxf(acc[m], 0.0f);
    }
    __syncthreads();

    // layer 2: thread owns (j = tid&127, half of the 32 rows)
    {
        const int j = tid & 127, mh = tid >> 7;
        float acc[16];
        const float bj = b2[j];
        #pragma unroll
        for (int m = 0; m < 16; m++) acc[m] = bj;
        const float4* z14 = (const float4*)(s + M_SM_Z1 + (mh * 16) * 256);
        #pragma unroll 2
        for (int k4 = 0; k4 < 64; k4++) {
            float w0 = W2[(4 * k4 + 0) * 128 + j];
            float w1 = W2[(4 * k4 + 1) * 128 + j];
            float w2 = W2[(4 * k4 + 2) * 128 + j];
            float w3 = W2[(4 * k4 + 3) * 128 + j];
            #pragma unroll
            for (int m = 0; m < 16; m++) {
                float4 zv = z14[m * 64 + k4];
                acc[m] = fmaf(w0, zv.x, acc[m]);
                acc[m] = fmaf(w1, zv.y, acc[m]);
                acc[m] = fmaf(w2, zv.z, acc[m]);
                acc[m] = fmaf(w3, zv.w, acc[m]);
            }
        }
        #pragma unroll
        for (int m = 0; m < 16; m++)
            s[M_SM_Z2 + (mh * 16 + m) * 129 + j] = fmaxf(acc[m], 0.0f);
    }
    __syncthreads();

    // layer 3 + transpose store: out[b][0][p][n] = pred[seq][p]
    for (int idx = tid; idx < 32 * NPRED; idx += 256) {
        const int m = idx & 31, pp = idx >> 5;
        float acc = s[M_SM_B3 + pp];
        const float* z2r = s + M_SM_Z2 + m * 129;
        #pragma unroll 8
        for (int k = 0; k < 128; k++)
            acc = fmaf(z2r[k], s[M_SM_W3 + k * 12 + pp], acc);
        const int seq = m0 + m;
        const int bb = seq >> 11, nn = seq & 2047;
        out[(size_t)bb * (NPRED * Nv) + pp * Nv + nn] = acc;
    }
}

// ---------------------------------------------------------------------------
// Launch
// ---------------------------------------------------------------------------
extern "C" void kernel_launch(void* const* d_in, const int* in_sizes, int n_in,
                              void* d_out, int out_size) {
    const float* x      = (const float*)d_in[0];
    const float* W_in   = (const float*)d_in[1];
    const float* b_in   = (const float*)d_in[2];
    const float* W_conv = (const float*)d_in[3];
    const float* b_conv = (const float*)d_in[4];
    const float* Wq     = (const float*)d_in[5];
    const float* bq     = (const float*)d_in[6];
    const float* Wk     = (const float*)d_in[7];
    const float* bk     = (const float*)d_in[8];
    const float* Wv     = (const float*)d_in[9];
    const float* bv     = (const float*)d_in[10];
    const float* W1     = (const float*)d_in[11];
    const float* b1     = (const float*)d_in[12];
    const float* W2     = (const float*)d_in[13];
    const float* b2     = (const float*)d_in[14];
    const float* W3     = (const float*)d_in[15];
    const float* b3     = (const float*)d_in[16];
    float* out = (float*)d_out;

    cudaFuncSetAttribute(main_kernel, cudaFuncAttributeMaxDynamicSharedMemorySize, MAIN_SMEM_BYTES);
    cudaFuncSetAttribute(mlp_kernel,  cudaFuncAttributeMaxDynamicSharedMemorySize, MLP_SMEM_BYTES);

    prep_kernel<<<42, 256>>>(W_in, b_in, W_conv, b_conv, Wq, bq, Wk, bk);
    main_kernel<<<304, 256, MAIN_SMEM_BYTES>>>(x, Wv, bv);
    mlp_kernel<<<SEQS / 32, 256, MLP_SMEM_BYTES>>>(W1, b1, W2, b2, W3, b3, out);
}

// round 4
// speedup vs baseline: 1.0147x; 1.0147x over previous
#include <cuda_runtime.h>

// ---------------------------------------------------------------------------
// Problem constants
// ---------------------------------------------------------------------------
constexpr int Bv = 16, Nv = 2048, Tv = 48, Ev = 32;
constexpr int C0 = 64, C1 = 64, H1 = 256, H2 = 128, NPRED = 12;
constexpr int SEQS = Bv * Nv;          // 32768
constexpr int PAIRS = SEQS / 2;        // 16384
constexpr int HSTRIDE = 65;            // padded row stride for h (bank-conflict free)
constexpr int HSIZE = Tv * HSTRIDE;    // 3120

// ---------------------------------------------------------------------------
// Device-global scratch (no allocations allowed)
// ---------------------------------------------------------------------------
__device__ float g_Wf[96 * 64];        // folded W_in @ W_conv[k], [k*32+e][c]
__device__ float g_WqkT[64 * 64];      // (Wk Wq^T) transposed: [c'][c]
__device__ float g_bqk[64];            // Wk @ bq
__device__ float g_vqb[64];            // Wq @ bk
__device__ float g_bias3[3 * 64];      // conv bias for t==0 / interior / t==47
__device__ float g_sqb;                // bq . bk
__device__ float g_ctx[(size_t)SEQS * 64];  // attention output, 8MB

// ---------------------------------------------------------------------------
// Prep kernel: fold weights (tiny, ~650K MACs)
// ---------------------------------------------------------------------------
__global__ void prep_kernel(const float* __restrict__ W_in, const float* __restrict__ b_in,
                            const float* __restrict__ W_conv, const float* __restrict__ b_conv,
                            const float* __restrict__ Wq, const float* __restrict__ bq,
                            const float* __restrict__ Wk, const float* __restrict__ bk) {
    int idx = blockIdx.x * blockDim.x + threadIdx.x;
    if (idx < 6144) {
        // Wf[k*32+e][c] = sum_m W_in[e][m] * W_conv[k][m][c]
        int row = idx >> 6, c = idx & 63;
        int k = row >> 5, e = row & 31;
        float s = 0.f;
        #pragma unroll 8
        for (int m = 0; m < 64; m++)
            s = fmaf(W_in[e * 64 + m], W_conv[(k * 64 + m) * 64 + c], s);
        g_Wf[row * 64 + c] = s;
    } else if (idx < 10240) {
        // WqkT[c'][c] = sum_d Wk[c][d] * Wq[c'][d]
        int i = idx - 6144;
        int cp = i >> 6, c = i & 63;
        float s = 0.f;
        #pragma unroll 8
        for (int d = 0; d < 64; d++)
            s = fmaf(Wk[c * 64 + d], Wq[cp * 64 + d], s);
        g_WqkT[cp * 64 + c] = s;
    } else if (idx < 10304) {
        int c = idx - 10240;
        float s = 0.f;
        #pragma unroll 8
        for (int d = 0; d < 64; d++) s = fmaf(Wk[c * 64 + d], bq[d], s);
        g_bqk[c] = s;
    } else if (idx < 10368) {
        int cp = idx - 10304;
        float s = 0.f;
        #pragma unroll 8
        for (int d = 0; d < 64; d++) s = fmaf(Wq[cp * 64 + d], bk[d], s);
        g_vqb[cp] = s;
    } else if (idx < 10560) {
        int i = idx - 10368;
        int which = i >> 6, c = i & 63;  // 0: t==0, 1: interior, 2: t==47
        float gb[3];
        #pragma unroll
        for (int k = 0; k < 3; k++) {
            float s = 0.f;
            #pragma unroll 8
            for (int m = 0; m < 64; m++)
                s = fmaf(b_in[m], W_conv[(k * 64 + m) * 64 + c], s);
            gb[k] = s;
        }
        float r = b_conv[c];
        if (which == 0)      r += gb[1] + gb[2];          // tap k=0 reads zero pad
        else if (which == 1) r += gb[0] + gb[1] + gb[2];
        else                 r += gb[0] + gb[1];          // tap k=2 reads zero pad
        g_bias3[which * 64 + c] = r;
    } else if (idx == 10560) {
        float s = 0.f;
        for (int d = 0; d < 64; d++) s = fmaf(bq[d], bk[d], s);
        g_sqb = s;
    }
}

// ---------------------------------------------------------------------------
// Main fused kernel smem layout (floats)
// ---------------------------------------------------------------------------
constexpr int SM_WF    = 0;                 // 6144
constexpr int SM_WQKT  = 6144;              // 4096
constexpr int SM_WV    = 10240;             // 4096
constexpr int SM_BV    = 14336;             // 64
constexpr int SM_BQK   = 14400;             // 64
constexpr int SM_VQB   = 14464;             // 64
constexpr int SM_BIAS3 = 14528;             // 192
constexpr int SM_X     = 14720;             // 2*1536 = 3072
constexpr int SM_H     = 17792;             // 2*3120 = 6240
constexpr int SM_KQ    = 24032;             // 128
constexpr int SM_SC    = 24160;             // 96
constexpr int SM_P     = 24256;             // 96
constexpr int SM_HB    = 24352;             // 128
constexpr int SM_MISC  = 24480;             // 8: bias[2], max[2], rinv[2], sqb
constexpr int MAIN_SMEM_FLOATS = 24488;
constexpr int MAIN_SMEM_BYTES  = MAIN_SMEM_FLOATS * 4;   // 97952

// Folded conv for 24 timesteps starting at compile-time T0.
// Thread owns column c; x values rolled through registers: 1 LDS + 3 FFMA per t.
template <int T0>
__device__ __forceinline__ void conv_part(const float* __restrict__ xs,
                                          const float* __restrict__ s,
                                          float* hacc, int c) {
    #pragma unroll
    for (int tt = 0; tt < 24; tt++) {
        int t = T0 + tt;
        const float* b = (t == 0) ? (s + SM_BIAS3)
                        : (t == 47 ? (s + SM_BIAS3 + 128) : (s + SM_BIAS3 + 64));
        hacc[tt] = b[c];
    }
    const float* wf = s + SM_WF + c;
    #pragma unroll 2
    for (int e = 0; e < 32; e++) {
        float w0 = wf[e * 64];
        float w1 = wf[(32 + e) * 64];
        float w2 = wf[(64 + e) * 64];
        const float* xb = xs + e;
        float xm = (T0 == 0) ? 0.0f : xb[(T0 - 1) * 32];
        float xc = xb[T0 * 32];
        #pragma unroll
        for (int tt = 0; tt < 24; tt++) {
            float xp = (T0 + tt == 47) ? 0.0f : xb[(T0 + tt + 1) * 32];
            hacc[tt] = fmaf(w0, xm, hacc[tt]);
            hacc[tt] = fmaf(w1, xc, hacc[tt]);
            hacc[tt] = fmaf(w2, xp, hacc[tt]);
            xm = xc; xc = xp;
        }
    }
}

// ---------------------------------------------------------------------------
// Main fused kernel: folded conv + collapsed attention, 2 sequences per iter
// ---------------------------------------------------------------------------
__global__ void __launch_bounds__(256, 2)
main_kernel(const float* __restrict__ x, const float* __restrict__ Wv,
            const float* __restrict__ bv) {
    extern __shared__ float s[];
    const int tid = threadIdx.x;

    // Stage weights into smem (once per block; blocks are persistent)
    for (int i = tid; i < 6144; i += 256) s[SM_WF + i] = g_Wf[i];
    for (int i = tid; i < 4096; i += 256) s[SM_WQKT + i] = g_WqkT[i];
    for (int i = tid; i < 4096; i += 256) s[SM_WV + i] = Wv[i];
    if (tid < 64) {
        s[SM_BV + tid]         = bv[tid];
        s[SM_BQK + tid]        = g_bqk[tid];
        s[SM_VQB + tid]        = g_vqb[tid];
        s[SM_BIAS3 + tid]       = g_bias3[tid];
        s[SM_BIAS3 + 64 + tid]  = g_bias3[64 + tid];
        s[SM_BIAS3 + 128 + tid] = g_bias3[128 + tid];
    }
    if (tid == 0) s[SM_MISC + 6] = g_sqb;

    const int c    = tid & 63;
    const int sub  = tid >> 6;   // 0..3
    const int useq = sub >> 1;   // conv: which of the 2 sequences
    const int tg   = sub & 1;    // conv: which 24-timestep half
    const int r    = tid & 127;  // attention role within half
    const int u    = tid >> 7;   // attention: which sequence

    int pi = blockIdx.x;
    // prefetch first pair's x (2 seqs contiguous = 3072 floats = 768 float4)
    float4 xr0, xr1, xr2;
    {
        const float4* src = (const float4*)(x + (size_t)pi * 3072);
        xr0 = src[tid]; xr1 = src[tid + 256]; xr2 = src[tid + 512];
    }

    for (; pi < PAIRS; pi += gridDim.x) {
        // commit prefetched x to smem, then prefetch next pair (hides DRAM latency)
        {
            float4* xd = (float4*)(s + SM_X);
            xd[tid] = xr0; xd[tid + 256] = xr1; xd[tid + 512] = xr2;
            int np = pi + gridDim.x;
            const float4* src = (const float4*)(x + (size_t)(np < PAIRS ? np : 0) * 3072);
            xr0 = src[tid]; xr1 = src[tid + 256]; xr2 = src[tid + 512];
        }
        __syncthreads();

        // ---- folded conv (fp32 fma-bound core) ----
        float hacc[24];
        const float* xs = s + SM_X + useq * 1536;
        float* hs = s + SM_H + useq * HSIZE;
        if (tg == 0) conv_part<0>(xs, s, hacc, c);
        else         conv_part<24>(xs, s, hacc, c);
        {
            const int t0 = tg * 24;
            #pragma unroll
            for (int tt = 0; tt < 24; tt++)
                hs[(t0 + tt) * HSTRIDE + c] = fmaxf(hacc[tt], 0.0f);
        }
        __syncthreads();

        // ---- collapsed attention (per 128-thread half) ----
        const float* hu = s + SM_H + u * HSIZE;
        float score = 0.f, p = 0.f;

        // stage 1: kq[c] = bqk + h47 . WqkT[:,c] ; bias = sqb + h47 . vqb
        if (r < 64) {
            float acc = s[SM_BQK + r];
            const float* h47 = hu + 47 * HSTRIDE;
            #pragma unroll 8
            for (int cp = 0; cp < 64; cp++)
                acc = fmaf(h47[cp], s[SM_WQKT + cp * 64 + r], acc);
            s[SM_KQ + u * 64 + r] = acc;
        } else if (r == 64) {
            float acc = s[SM_MISC + 6];
            const float* h47 = hu + 47 * HSTRIDE;
            #pragma unroll 8
            for (int cp = 0; cp < 64; cp++)
                acc = fmaf(h47[cp], s[SM_VQB + cp], acc);
            s[SM_MISC + u] = acc;
        }
        __syncthreads();

        // stage 2: scores[s] = (h[s].kq + bias) / 8
        if (r < 48) {
            float acc = 0.f;
            const float* hrow = hu + r * HSTRIDE;
            #pragma unroll 8
            for (int cc = 0; cc < 64; cc++)
                acc = fmaf(hrow[cc], s[SM_KQ + u * 64 + cc], acc);
            score = (acc + s[SM_MISC + u]) * 0.125f;
            s[SM_SC + u * 48 + r] = score;
        }
        __syncthreads();

        // stage 3: max-reduce (one warp per half)
        if (r < 32) {
            float v = s[SM_SC + u * 48 + r];
            if (r < 16) v = fmaxf(v, s[SM_SC + u * 48 + 32 + r]);
            #pragma unroll
            for (int off = 16; off; off >>= 1)
                v = fmaxf(v, __shfl_xor_sync(0xffffffffu, v, off));
            if (r == 0) s[SM_MISC + 2 + u] = v;
        }
        __syncthreads();

        // stage 4: exp
        if (r < 48) {
            p = __expf(score - s[SM_MISC + 2 + u]);
            s[SM_P + u * 48 + r] = p;
        }
        __syncthreads();

        // stage 5: sum-reduce -> 1/sum
        if (r < 32) {
            float v = s[SM_P + u * 48 + r];
            if (r < 16) v += s[SM_P + u * 48 + 32 + r];
            #pragma unroll
            for (int off = 16; off; off >>= 1)
                v += __shfl_xor_sync(0xffffffffu, v, off);
            if (r == 0) s[SM_MISC + 4 + u] = 1.0f / v;
        }
        __syncthreads();

        // stage 6: hbar[c] = (sum_s p[s] h[s][c]) / sum
        if (r < 64) {
            float acc = 0.f;
            #pragma unroll 8
            for (int ss = 0; ss < 48; ss++)
                acc = fmaf(s[SM_P + u * 48 + ss], hu[ss * HSTRIDE + r], acc);
            s[SM_HB + u * 64 + r] = acc * s[SM_MISC + 4 + u];
        }
        __syncthreads();

        // stage 7: ctx = hbar @ Wv + bv  -> global scratch
        if (r < 64) {
            float acc = s[SM_BV + r];
            #pragma unroll 8
            for (int cc = 0; cc < 64; cc++)
                acc = fmaf(s[SM_HB + u * 64 + cc], s[SM_WV + cc * 64 + r], acc);
            g_ctx[(size_t)(2 * pi + u) * 64 + r] = acc;
        }
        // no trailing sync needed: next-iter writes are fenced by the loop-top sync
    }
}

// ---------------------------------------------------------------------------
// MLP kernel: 32 sequences per block; W1/W2 streamed from L2 (resident)
// ---------------------------------------------------------------------------
constexpr int M_SM_CTX = 0;        // 32*64  = 2048
constexpr int M_SM_Z1  = 2048;     // 32*256 = 8192
constexpr int M_SM_Z2  = 10240;    // 32*129 = 4128 (padded: conflict-free L3 reads)
constexpr int M_SM_W3  = 14368;    // 128*12 = 1536
constexpr int M_SM_B3  = 15904;    // 12
constexpr int MLP_SMEM_FLOATS = 15920;
constexpr int MLP_SMEM_BYTES  = MLP_SMEM_FLOATS * 4;    // 63680

__global__ void __launch_bounds__(256)
mlp_kernel(const float* __restrict__ W1, const float* __restrict__ b1,
           const float* __restrict__ W2, const float* __restrict__ b2,
           const float* __restrict__ W3, const float* __restrict__ b3,
           float* __restrict__ out) {
    extern __shared__ float s[];
    const int tid = threadIdx.x;
    const int m0 = blockIdx.x * 32;

    {
        const float4* src = (const float4*)(g_ctx + (size_t)m0 * 64);
        float4* dst = (float4*)(s + M_SM_CTX);
        dst[tid] = src[tid];
        dst[tid + 256] = src[tid + 256];
    }
    for (int i = tid; i < 1536; i += 256) s[M_SM_W3 + i] = W3[i];
    if (tid < 12) s[M_SM_B3 + tid] = b3[tid];
    __syncthreads();

    // layer 1: z1[m][j] = relu(ctx[m] . W1[:,j] + b1[j]), thread owns column j=tid
    {
        float acc[32];
        const float bj = b1[tid];
        #pragma unroll
        for (int m = 0; m < 32; m++) acc[m] = bj;
        const float4* ctx4 = (const float4*)(s + M_SM_CTX);
        #pragma unroll 4
        for (int k4 = 0; k4 < 16; k4++) {
            float w0 = W1[(4 * k4 + 0) * 256 + tid];
            float w1 = W1[(4 * k4 + 1) * 256 + tid];
            float w2 = W1[(4 * k4 + 2) * 256 + tid];
            float w3 = W1[(4 * k4 + 3) * 256 + tid];
            #pragma unroll
            for (int m = 0; m < 32; m++) {
                float4 cv = ctx4[m * 16 + k4];
                acc[m] = fmaf(w0, cv.x, acc[m]);
                acc[m] = fmaf(w1, cv.y, acc[m]);
                acc[m] = fmaf(w2, cv.z, acc[m]);
                acc[m] = fmaf(w3, cv.w, acc[m]);
            }
        }
        #pragma unroll
        for (int m = 0; m < 32; m++)
            s[M_SM_Z1 + m * 256 + tid] = fmaxf(acc[m], 0.0f);
    }
    __syncthreads();

    // layer 2: thread owns (j = tid&127, half of the 32 rows)
    {
        const int j = tid & 127, mh = tid >> 7;
        float acc[16];
        const float bj = b2[j];
        #pragma unroll
        for (int m = 0; m < 16; m++) acc[m] = bj;
        const float4* z14 = (const float4*)(s + M_SM_Z1 + (mh * 16) * 256);
        #pragma unroll 2
        for (int k4 = 0; k4 < 64; k4++) {
            float w0 = W2[(4 * k4 + 0) * 128 + j];
            float w1 = W2[(4 * k4 + 1) * 128 + j];
            float w2 = W2[(4 * k4 + 2) * 128 + j];
            float w3 = W2[(4 * k4 + 3) * 128 + j];
            #pragma unroll
            for (int m = 0; m < 16; m++) {
                float4 zv = z14[m * 64 + k4];
                acc[m] = fmaf(w0, zv.x, acc[m]);
                acc[m] = fmaf(w1, zv.y, acc[m]);
                acc[m] = fmaf(w2, zv.z, acc[m]);
                acc[m] = fmaf(w3, zv.w, acc[m]);
            }
        }
        #pragma unroll
        for (int m = 0; m < 16; m++)
            s[M_SM_Z2 + (mh * 16 + m) * 129 + j] = fmaxf(acc[m], 0.0f);
    }
    __syncthreads();

    // layer 3 + transpose store: out[b][0][p][n] = pred[seq][p]
    for (int idx = tid; idx < 32 * NPRED; idx += 256) {
        const int m = idx & 31, pp = idx >> 5;
        float acc = s[M_SM_B3 + pp];
        const float* z2r = s + M_SM_Z2 + m * 129;
        #pragma unroll 8
        for (int k = 0; k < 128; k++)
            acc = fmaf(z2r[k], s[M_SM_W3 + k * 12 + pp], acc);
        const int seq = m0 + m;
        const int bb = seq >> 11, nn = seq & 2047;
        out[(size_t)bb * (NPRED * Nv) + pp * Nv + nn] = acc;
    }
}

// ---------------------------------------------------------------------------
// Launch
// ---------------------------------------------------------------------------
extern "C" void kernel_launch(void* const* d_in, const int* in_sizes, int n_in,
                              void* d_out, int out_size) {
    const float* x      = (const float*)d_in[0];
    const float* W_in   = (const float*)d_in[1];
    const float* b_in   = (const float*)d_in[2];
    const float* W_conv = (const float*)d_in[3];
    const float* b_conv = (const float*)d_in[4];
    const float* Wq     = (const float*)d_in[5];
    const float* bq     = (const float*)d_in[6];
    const float* Wk     = (const float*)d_in[7];
    const float* bk     = (const float*)d_in[8];
    const float* Wv     = (const float*)d_in[9];
    const float* bv     = (const float*)d_in[10];
    const float* W1     = (const float*)d_in[11];
    const float* b1     = (const float*)d_in[12];
    const float* W2     = (const float*)d_in[13];
    const float* b2     = (const float*)d_in[14];
    const float* W3     = (const float*)d_in[15];
    const float* b3     = (const float*)d_in[16];
    float* out = (float*)d_out;

    cudaFuncSetAttribute(main_kernel, cudaFuncAttributeMaxDynamicSharedMemorySize, MAIN_SMEM_BYTES);
    cudaFuncSetAttribute(mlp_kernel,  cudaFuncAttributeMaxDynamicSharedMemorySize, MLP_SMEM_BYTES);

    prep_kernel<<<42, 256>>>(W_in, b_in, W_conv, b_conv, Wq, bq, Wk, bk);
    main_kernel<<<304, 256, MAIN_SMEM_BYTES>>>(x, Wv, bv);
    mlp_kernel<<<SEQS / 32, 256, MLP_SMEM_BYTES>>>(W1, b1, W2, b2, W3, b3, out);
}